// round 5
// baseline (speedup 1.0000x reference)
#include <cuda_runtime.h>
#include <cuda_bf16.h>

// out[b, i] = x[b, i] * weight[i] + bias[i]
// BATCH = 8192, IN_SIZE = 4096, fp32.
//
// R5 design: R2 shape (best measured), store policy changed.
//  - x reads:  __ldcs (evict-first streaming; touch-once, keep L2 free)
//  - out stores: DEFAULT write-back -> dirty lines stay in L2; across graph
//    replays the same lines are overwritten in place, cutting DRAM write
//    traffic (out = 134 MB vs L2 = 126 MB, near-full residency)
//  - block = 256 threads, fixed 256-float4 column strip, w/b in registers
//  - 4 rows per block, loads front-batched (MLP_p1 = 4), grid (4, 2048)

static constexpr int IN_SIZE   = 4096;
static constexpr int IN_SIZE4  = IN_SIZE / 4;        // 1024 float4 per row
static constexpr int THREADS   = 256;
static constexpr int COL_GRPS  = IN_SIZE4 / THREADS; // 4
static constexpr int ROWS_PER_BLOCK = 4;

__global__ __launch_bounds__(THREADS)
void diag_linear_kernel(const float4* __restrict__ x4,
                        const float4* __restrict__ w4,
                        const float4* __restrict__ b4,
                        float4* __restrict__ out4)
{
    const int col4 = blockIdx.x * THREADS + threadIdx.x;      // 0..1023
    const int row0 = blockIdx.y * ROWS_PER_BLOCK;

    const float4 wv = __ldg(&w4[col4]);
    const float4 bv = __ldg(&b4[col4]);

    const long base = (long)row0 * IN_SIZE4 + col4;

    // Front-batched loads: 4 independent LDG.128 in flight
    float4 v0 = __ldcs(&x4[base + 0L * IN_SIZE4]);
    float4 v1 = __ldcs(&x4[base + 1L * IN_SIZE4]);
    float4 v2 = __ldcs(&x4[base + 2L * IN_SIZE4]);
    float4 v3 = __ldcs(&x4[base + 3L * IN_SIZE4]);

    v0.x = fmaf(v0.x, wv.x, bv.x); v0.y = fmaf(v0.y, wv.y, bv.y);
    v0.z = fmaf(v0.z, wv.z, bv.z); v0.w = fmaf(v0.w, wv.w, bv.w);

    v1.x = fmaf(v1.x, wv.x, bv.x); v1.y = fmaf(v1.y, wv.y, bv.y);
    v1.z = fmaf(v1.z, wv.z, bv.z); v1.w = fmaf(v1.w, wv.w, bv.w);

    v2.x = fmaf(v2.x, wv.x, bv.x); v2.y = fmaf(v2.y, wv.y, bv.y);
    v2.z = fmaf(v2.z, wv.z, bv.z); v2.w = fmaf(v2.w, wv.w, bv.w);

    v3.x = fmaf(v3.x, wv.x, bv.x); v3.y = fmaf(v3.y, wv.y, bv.y);
    v3.z = fmaf(v3.z, wv.z, bv.z); v3.w = fmaf(v3.w, wv.w, bv.w);

    // Default write-back stores: dirty lines persist in L2 across replays
    out4[base + 0L * IN_SIZE4] = v0;
    out4[base + 1L * IN_SIZE4] = v1;
    out4[base + 2L * IN_SIZE4] = v2;
    out4[base + 3L * IN_SIZE4] = v3;
}

extern "C" void kernel_launch(void* const* d_in, const int* in_sizes, int n_in,
                              void* d_out, int out_size)
{
    const float* x      = (const float*)d_in[0];
    const float* weight = (const float*)d_in[1];
    const float* bias   = (const float*)d_in[2];
    float* out          = (float*)d_out;

    const int n    = in_sizes[0];            // BATCH * IN_SIZE
    const int rows = n / IN_SIZE;            // 8192

    dim3 grid(COL_GRPS, rows / ROWS_PER_BLOCK);   // (4, 2048) = 8192 CTAs
    diag_linear_kernel<<<grid, THREADS>>>(
        (const float4*)x, (const float4*)weight, (const float4*)bias,
        (float4*)out);
}

// round 6
// speedup vs baseline: 1.0247x; 1.0247x over previous
#include <cuda_runtime.h>
#include <cuda_bf16.h>

// out[b, i] = x[b, i] * weight[i] + bias[i]
// BATCH = 8192, IN_SIZE = 4096, fp32. HBM-bound.
//
// R6 design: Blackwell 256-bit vector ld/st (LDG.E.256 / STG.E.256).
//  - each thread owns 8 consecutive floats (32B, aligned)
//  - 2 rows per block, loads front-batched (64B in flight/thread, = R2)
//  - halves LSU instruction count / L1tex wavefronts vs float4 version
//  - grid = (2 col-groups, 4096 row-groups) = 8192 CTAs, no tail

static constexpr int IN_SIZE   = 4096;
static constexpr int IN_SIZE8  = IN_SIZE / 8;        // 512 float8 per row
static constexpr int THREADS   = 256;
static constexpr int COL_GRPS  = IN_SIZE8 / THREADS; // 2
static constexpr int ROWS_PER_BLOCK = 2;

__device__ __forceinline__ void ldg256_cs(const float* __restrict__ p, float* v)
{
    asm volatile("ld.global.cs.v8.f32 {%0,%1,%2,%3,%4,%5,%6,%7}, [%8];"
                 : "=f"(v[0]), "=f"(v[1]), "=f"(v[2]), "=f"(v[3]),
                   "=f"(v[4]), "=f"(v[5]), "=f"(v[6]), "=f"(v[7])
                 : "l"(p));
}

__device__ __forceinline__ void ldg256_nc(const float* __restrict__ p, float* v)
{
    asm volatile("ld.global.nc.v8.f32 {%0,%1,%2,%3,%4,%5,%6,%7}, [%8];"
                 : "=f"(v[0]), "=f"(v[1]), "=f"(v[2]), "=f"(v[3]),
                   "=f"(v[4]), "=f"(v[5]), "=f"(v[6]), "=f"(v[7])
                 : "l"(p));
}

__device__ __forceinline__ void stg256_cs(float* __restrict__ p, const float* v)
{
    asm volatile("st.global.cs.v8.f32 [%0], {%1,%2,%3,%4,%5,%6,%7,%8};"
                 :: "l"(p),
                    "f"(v[0]), "f"(v[1]), "f"(v[2]), "f"(v[3]),
                    "f"(v[4]), "f"(v[5]), "f"(v[6]), "f"(v[7])
                 : "memory");
}

__global__ __launch_bounds__(THREADS)
void diag_linear_kernel(const float* __restrict__ x,
                        const float* __restrict__ w,
                        const float* __restrict__ b,
                        float* __restrict__ out)
{
    const int col8 = blockIdx.x * THREADS + threadIdx.x;   // 0..511
    const int row0 = blockIdx.y * ROWS_PER_BLOCK;

    // Per-thread constants for this 8-float column slice
    float wv[8], bv[8];
    ldg256_nc(w + col8 * 8, wv);
    ldg256_nc(b + col8 * 8, bv);

    const long base = ((long)row0 * IN_SIZE + col8 * 8);

    // Front-batched 256-bit loads: 2 independent LDG.256 in flight
    float v0[8], v1[8];
    ldg256_cs(x + base,            v0);
    ldg256_cs(x + base + IN_SIZE,  v1);

#pragma unroll
    for (int i = 0; i < 8; i++) v0[i] = fmaf(v0[i], wv[i], bv[i]);
#pragma unroll
    for (int i = 0; i < 8; i++) v1[i] = fmaf(v1[i], wv[i], bv[i]);

    stg256_cs(out + base,           v0);
    stg256_cs(out + base + IN_SIZE, v1);
}

extern "C" void kernel_launch(void* const* d_in, const int* in_sizes, int n_in,
                              void* d_out, int out_size)
{
    const float* x      = (const float*)d_in[0];
    const float* weight = (const float*)d_in[1];
    const float* bias   = (const float*)d_in[2];
    float* out          = (float*)d_out;

    const int n    = in_sizes[0];            // BATCH * IN_SIZE
    const int rows = n / IN_SIZE;            // 8192

    dim3 grid(COL_GRPS, rows / ROWS_PER_BLOCK);   // (2, 4096) = 8192 CTAs
    diag_linear_kernel<<<grid, THREADS>>>(x, weight, bias, out);
}